// round 6
// baseline (speedup 1.0000x reference)
#include <cuda_runtime.h>
#include <cstdint>

#define B_ 4
#define H_ 16
#define S_ 2048
#define D_ 64
#define BR 128           // query rows per CTA (8 warps x 16)
#define BC 64            // key cols per tile

// dynamic smem layout (bytes)
#define SM_F32K 0
#define SM_F32V 16384
#define SM_K16  32768                 // 64 rows x 144B (also Q staging rows 0..63)
#define SM_V16  (32768 + 9216)        // 64 rows x 144B (also Q staging rows 64..127)
#define SM_BYTES (32768 + 9216 + 9216)

#define RSTRIDE 144                   // fp16 row stride in bytes (64 halves + 8 pad)

static __device__ __forceinline__ float ex2f(float x) {
    float y; asm("ex2.approx.f32 %0, %1;" : "=f"(y) : "f"(x)); return y;
}
// pack {lo, hi} floats -> f16x2 (lo in low 16 bits)
static __device__ __forceinline__ uint32_t pk(float lo, float hi) {
    uint32_t d; asm("cvt.rn.f16x2.f32 %0, %1, %2;" : "=r"(d) : "f"(hi), "f"(lo)); return d;
}
static __device__ __forceinline__ uint32_t s2u(const void* p) {
    uint32_t a;
    asm("{.reg .u64 t; cvta.to.shared.u64 t, %1; cvt.u32.u64 %0, t;}" : "=r"(a) : "l"(p));
    return a;
}
static __device__ __forceinline__ void cpa16(uint32_t dst, const void* src) {
    asm volatile("cp.async.cg.shared.global [%0], [%1], 16;" :: "r"(dst), "l"(src));
}
static __device__ __forceinline__ void ldm4(uint32_t* r, uint32_t a) {
    asm volatile("ldmatrix.sync.aligned.m8n8.x4.shared.b16 {%0,%1,%2,%3}, [%4];"
                 : "=r"(r[0]), "=r"(r[1]), "=r"(r[2]), "=r"(r[3]) : "r"(a));
}
static __device__ __forceinline__ void ldm4t(uint32_t* r, uint32_t a) {
    asm volatile("ldmatrix.sync.aligned.m8n8.x4.trans.shared.b16 {%0,%1,%2,%3}, [%4];"
                 : "=r"(r[0]), "=r"(r[1]), "=r"(r[2]), "=r"(r[3]) : "r"(a));
}
static __device__ __forceinline__ void mma16816(float* c, const uint32_t* a,
                                                uint32_t b0, uint32_t b1) {
    asm volatile(
        "mma.sync.aligned.m16n8k16.row.col.f32.f16.f16.f32 "
        "{%0,%1,%2,%3},{%4,%5,%6,%7},{%8,%9},{%0,%1,%2,%3};"
        : "+f"(c[0]), "+f"(c[1]), "+f"(c[2]), "+f"(c[3])
        : "r"(a[0]), "r"(a[1]), "r"(a[2]), "r"(a[3]), "r"(b0), "r"(b1));
}

__global__ __launch_bounds__(256, 2)
void fa_fp16_v3(const float* __restrict__ Q,
                const float* __restrict__ K,
                const float* __restrict__ V,
                const int* __restrict__ to_mask,
                float* __restrict__ O) {
    extern __shared__ char smem[];
    const uint32_t sb = s2u(smem);

    const int tid  = threadIdx.x;
    const int w    = tid >> 5;
    const int lane = tid & 31;
    const int g    = lane >> 2;
    const int t    = lane & 3;
    const int qt   = (int)gridDim.x - 1 - (int)blockIdx.x;   // heavy tiles first
    const int bh   = blockIdx.y;
    const int msk  = to_mask[0];

    const float* Qb = Q + ((size_t)bh * S_ + (size_t)qt * BR) * D_;
    const float* Kb = K + (size_t)bh * S_ * D_;
    const float* Vb = V + (size_t)bh * S_ * D_;

    const int ntiles = msk ? (2 * qt + 2) : (S_ / BC);

    // ---- prologue: cp.async tile 0 (f32 K,V; 1024 float4 each) ----
    #pragma unroll
    for (int i = 0; i < 4; i++) {
        int f = tid + i * 256;                 // float4 index
        cpa16(sb + SM_F32K + f * 16, Kb + f * 4);
        cpa16(sb + SM_F32V + f * 16, Vb + f * 4);
    }
    asm volatile("cp.async.commit_group;" ::: "memory");

    // ---- stage Q (128x64): f32 gmem -> scaled fp16 spanning K16+V16 region ----
    const float QSC = 0.125f * 1.44269504088896341f;      // 1/sqrt(64) * log2(e)
    {
        const float4* Q4 = reinterpret_cast<const float4*>(Qb);
        char* q16 = smem + SM_K16;
        #pragma unroll
        for (int i = 0; i < 4; i++) {
            int ci = tid + i * 256;                        // 16B-chunk idx (0..1023)
            float4 x = Q4[2 * ci];
            float4 y = Q4[2 * ci + 1];
            uint4 h;
            h.x = pk(x.x * QSC, x.y * QSC);
            h.y = pk(x.z * QSC, x.w * QSC);
            h.z = pk(y.x * QSC, y.y * QSC);
            h.w = pk(y.z * QSC, y.w * QSC);
            *reinterpret_cast<uint4*>(q16 + (ci >> 3) * RSTRIDE + (ci & 7) * 16) = h;
        }
    }
    __syncthreads();

    // one m16 row-tile per warp: rows w*16 + [0..16)
    uint32_t qa[4][4];
    {
        uint32_t qbase = sb + SM_K16 + (w * 16 + (lane & 15)) * RSTRIDE + (lane >> 4) * 16;
        #pragma unroll
        for (int ks = 0; ks < 4; ks++) ldm4(qa[ks], qbase + ks * 32);
    }

    float o[8][4];
    #pragma unroll
    for (int nt = 0; nt < 8; nt++) { o[nt][0]=0.f; o[nt][1]=0.f; o[nt][2]=0.f; o[nt][3]=0.f; }
    float m0 = -1e30f, m1 = -1e30f, l0 = 0.f, l1 = 0.f;

    // per-thread ldmatrix base addrs
    const uint32_t kfb = sb + SM_K16 + (lane & 7) * RSTRIDE + (lane >> 3) * 16;
    const uint32_t vfb = sb + SM_V16 + lane * RSTRIDE;

    for (int j = 0; j < ntiles; j++) {
        asm volatile("cp.async.wait_group 0;" ::: "memory");
        __syncthreads();                         // tile j f32 visible; prev compute done

        // ---- convert f32 -> fp16 (K and V, 144B-stride rows) ----
        {
            const float4* K4 = reinterpret_cast<const float4*>(smem + SM_F32K);
            const float4* V4 = reinterpret_cast<const float4*>(smem + SM_F32V);
            char* k16 = smem + SM_K16;
            char* v16 = smem + SM_V16;
            #pragma unroll
            for (int i = 0; i < 2; i++) {
                int ci = tid + i * 256;
                int dst = (ci >> 3) * RSTRIDE + (ci & 7) * 16;
                float4 x = K4[2 * ci], y = K4[2 * ci + 1];
                uint4 h;
                h.x = pk(x.x, x.y); h.y = pk(x.z, x.w);
                h.z = pk(y.x, y.y); h.w = pk(y.z, y.w);
                *reinterpret_cast<uint4*>(k16 + dst) = h;
                x = V4[2 * ci]; y = V4[2 * ci + 1];
                h.x = pk(x.x, x.y); h.y = pk(x.z, x.w);
                h.z = pk(y.x, y.y); h.w = pk(y.z, y.w);
                *reinterpret_cast<uint4*>(v16 + dst) = h;
            }
        }
        __syncthreads();

        // ---- prefetch tile j+1 (overlaps with compute below) ----
        if (j + 1 < ntiles) {
            const float* Kt = Kb + (size_t)(j + 1) * BC * D_;
            const float* Vt = Vb + (size_t)(j + 1) * BC * D_;
            #pragma unroll
            for (int i = 0; i < 4; i++) {
                int f = tid + i * 256;
                cpa16(sb + SM_F32K + f * 16, Kt + f * 4);
                cpa16(sb + SM_F32V + f * 16, Vt + f * 4);
            }
            asm volatile("cp.async.commit_group;" ::: "memory");
        }

        // ---- S = Q K^T  (32 MMA + 16 ldmatrix per warp) ----
        float s[8][4];
        #pragma unroll
        for (int nt = 0; nt < 8; nt++) { s[nt][0]=0.f; s[nt][1]=0.f; s[nt][2]=0.f; s[nt][3]=0.f; }
        #pragma unroll
        for (int nt = 0; nt < 8; nt++) {
            uint32_t b[8];
            ldm4(b,     kfb + nt * (8 * RSTRIDE));          // k chunks 0..3
            ldm4(b + 4, kfb + nt * (8 * RSTRIDE) + 64);     // k chunks 4..7
            mma16816(s[nt], qa[0], b[0], b[1]);
            mma16816(s[nt], qa[1], b[2], b[3]);
            mma16816(s[nt], qa[2], b[4], b[5]);
            mma16816(s[nt], qa[3], b[6], b[7]);
        }

        // ---- causal mask (diagonal region spans key tiles 2qt, 2qt+1) ----
        if (msk && j >= 2 * qt) {
            const int row0 = qt * BR + w * 16 + g;
            #pragma unroll
            for (int nt = 0; nt < 8; nt++) {
                int col = j * BC + nt * 8 + 2 * t;
                if (col     > row0)     s[nt][0] = -1e30f;
                if (col + 1 > row0)     s[nt][1] = -1e30f;
                if (col     > row0 + 8) s[nt][2] = -1e30f;
                if (col + 1 > row0 + 8) s[nt][3] = -1e30f;
            }
        }

        // ---- online softmax (base-2), tree reductions ----
        float a0, a1, b0_, b1_;
        a0 = fmaxf(fmaxf(s[0][0], s[0][1]), fmaxf(s[1][0], s[1][1]));
        b0_ = fmaxf(fmaxf(s[2][0], s[2][1]), fmaxf(s[3][0], s[3][1]));
        a1 = fmaxf(fmaxf(s[4][0], s[4][1]), fmaxf(s[5][0], s[5][1]));
        b1_ = fmaxf(fmaxf(s[6][0], s[6][1]), fmaxf(s[7][0], s[7][1]));
        float tm0 = fmaxf(fmaxf(a0, b0_), fmaxf(a1, b1_));
        a0 = fmaxf(fmaxf(s[0][2], s[0][3]), fmaxf(s[1][2], s[1][3]));
        b0_ = fmaxf(fmaxf(s[2][2], s[2][3]), fmaxf(s[3][2], s[3][3]));
        a1 = fmaxf(fmaxf(s[4][2], s[4][3]), fmaxf(s[5][2], s[5][3]));
        b1_ = fmaxf(fmaxf(s[6][2], s[6][3]), fmaxf(s[7][2], s[7][3]));
        float tm1 = fmaxf(fmaxf(a0, b0_), fmaxf(a1, b1_));
        #pragma unroll
        for (int off = 1; off < 4; off <<= 1) {
            tm0 = fmaxf(tm0, __shfl_xor_sync(0xffffffffu, tm0, off));
            tm1 = fmaxf(tm1, __shfl_xor_sync(0xffffffffu, tm1, off));
        }
        const float mn0 = fmaxf(m0, tm0), mn1 = fmaxf(m1, tm1);
        const float c0 = ex2f(m0 - mn0), c1 = ex2f(m1 - mn1);
        #pragma unroll
        for (int nt = 0; nt < 8; nt++) {
            s[nt][0] = ex2f(s[nt][0] - mn0);
            s[nt][1] = ex2f(s[nt][1] - mn0);
            s[nt][2] = ex2f(s[nt][2] - mn1);
            s[nt][3] = ex2f(s[nt][3] - mn1);
        }
        // 4-way partial sums (short dependency chains)
        float p0 = (s[0][0] + s[0][1]) + (s[1][0] + s[1][1]);
        float p1 = (s[2][0] + s[2][1]) + (s[3][0] + s[3][1]);
        float p2 = (s[4][0] + s[4][1]) + (s[5][0] + s[5][1]);
        float p3 = (s[6][0] + s[6][1]) + (s[7][0] + s[7][1]);
        float ps0 = (p0 + p1) + (p2 + p3);
        p0 = (s[0][2] + s[0][3]) + (s[1][2] + s[1][3]);
        p1 = (s[2][2] + s[2][3]) + (s[3][2] + s[3][3]);
        p2 = (s[4][2] + s[4][3]) + (s[5][2] + s[5][3]);
        p3 = (s[6][2] + s[6][3]) + (s[7][2] + s[7][3]);
        float ps1 = (p0 + p1) + (p2 + p3);

        l0 = l0 * c0 + ps0;  l1 = l1 * c1 + ps1;
        m0 = mn0;            m1 = mn1;
        #pragma unroll
        for (int nt = 0; nt < 8; nt++) {
            o[nt][0] *= c0; o[nt][1] *= c0; o[nt][2] *= c1; o[nt][3] *= c1;
        }

        // ---- P C-frags -> A-frags (register packs) ----
        uint32_t pa[4][4];
        #pragma unroll
        for (int ks = 0; ks < 4; ks++) {
            pa[ks][0] = pk(s[2*ks][0],   s[2*ks][1]);
            pa[ks][1] = pk(s[2*ks][2],   s[2*ks][3]);
            pa[ks][2] = pk(s[2*ks+1][0], s[2*ks+1][1]);
            pa[ks][3] = pk(s[2*ks+1][2], s[2*ks+1][3]);
        }

        // ---- O += P V  (32 MMA + 16 ldmatrix.trans per warp) ----
        #pragma unroll
        for (int nt = 0; nt < 8; nt++) {
            uint32_t b[8];
            ldm4t(b,     vfb + nt * 16);                    // s rows 0..31
            ldm4t(b + 4, vfb + nt * 16 + 32 * RSTRIDE);     // s rows 32..63
            mma16816(o[nt], pa[0], b[0], b[1]);
            mma16816(o[nt], pa[1], b[2], b[3]);
            mma16816(o[nt], pa[2], b[4], b[5]);
            mma16816(o[nt], pa[3], b[6], b[7]);
        }
    }

    // ---- epilogue ----
    #pragma unroll
    for (int off = 1; off < 4; off <<= 1) {
        l0 += __shfl_xor_sync(0xffffffffu, l0, off);
        l1 += __shfl_xor_sync(0xffffffffu, l1, off);
    }
    const float inv0 = 1.f / l0, inv1 = 1.f / l1;
    const int row0 = qt * BR + w * 16 + g;
    float* Ob = O + (size_t)bh * S_ * D_;
    #pragma unroll
    for (int nt = 0; nt < 8; nt++) {
        int col = nt * 8 + 2 * t;
        *reinterpret_cast<float2*>(Ob + (size_t)row0 * D_ + col) =
            make_float2(o[nt][0] * inv0, o[nt][1] * inv0);
        *reinterpret_cast<float2*>(Ob + (size_t)(row0 + 8) * D_ + col) =
            make_float2(o[nt][2] * inv1, o[nt][3] * inv1);
    }
}

extern "C" void kernel_launch(void* const* d_in, const int* in_sizes, int n_in,
                              void* d_out, int out_size) {
    const float* Q = (const float*)d_in[0];
    const float* K = (const float*)d_in[1];
    const float* V = (const float*)d_in[2];
    const int* msk = (const int*)d_in[3];
    float* O = (float*)d_out;

    cudaFuncSetAttribute(fa_fp16_v3, cudaFuncAttributeMaxDynamicSharedMemorySize, SM_BYTES);
    dim3 grid(S_ / BR, B_ * H_);
    fa_fp16_v3<<<grid, 256, SM_BYTES>>>(Q, K, V, msk, O);
}

// round 7
// speedup vs baseline: 1.3553x; 1.3553x over previous
#include <cuda_runtime.h>
#include <cstdint>

#define B_ 4
#define H_ 16
#define S_ 2048
#define D_ 64
#define BR 128           // query rows per CTA (4 warps x 32)
#define BC 64            // key cols per tile
#define RSTRIDE 144      // fp16 row stride in bytes (64 halves + 8 pad)
#define BUFB 18432       // bytes per K+V fp16 buffer pair (2 x 64 x 144)
#define SM_BYTES (2 * BUFB)
#define ONES16 0x3C003C00u

// fp16 copies of K and V (filled by prepass each launch)
__device__ __align__(16) unsigned short g_k16[B_ * H_ * S_ * D_];
__device__ __align__(16) unsigned short g_v16[B_ * H_ * S_ * D_];

static __device__ __forceinline__ float ex2f(float x) {
    float y; asm("ex2.approx.f32 %0, %1;" : "=f"(y) : "f"(x)); return y;
}
static __device__ __forceinline__ uint32_t hex2(uint32_t x) {
    uint32_t y; asm("ex2.approx.f16x2 %0, %1;" : "=r"(y) : "r"(x)); return y;
}
// pack {lo, hi} floats -> f16x2 (lo in low 16 bits)
static __device__ __forceinline__ uint32_t pk(float lo, float hi) {
    uint32_t d; asm("cvt.rn.f16x2.f32 %0, %1, %2;" : "=r"(d) : "f"(hi), "f"(lo)); return d;
}
static __device__ __forceinline__ uint32_t s2u(const void* p) {
    uint32_t a;
    asm("{.reg .u64 t; cvta.to.shared.u64 t, %1; cvt.u32.u64 %0, t;}" : "=r"(a) : "l"(p));
    return a;
}
static __device__ __forceinline__ void cpa16(uint32_t dst, const void* src) {
    asm volatile("cp.async.cg.shared.global [%0], [%1], 16;" :: "r"(dst), "l"(src));
}
static __device__ __forceinline__ void ldm4(uint32_t* r, uint32_t a) {
    asm volatile("ldmatrix.sync.aligned.m8n8.x4.shared.b16 {%0,%1,%2,%3}, [%4];"
                 : "=r"(r[0]), "=r"(r[1]), "=r"(r[2]), "=r"(r[3]) : "r"(a));
}
static __device__ __forceinline__ void ldm4t(uint32_t* r, uint32_t a) {
    asm volatile("ldmatrix.sync.aligned.m8n8.x4.trans.shared.b16 {%0,%1,%2,%3}, [%4];"
                 : "=r"(r[0]), "=r"(r[1]), "=r"(r[2]), "=r"(r[3]) : "r"(a));
}
static __device__ __forceinline__ void mma16816(float* c, const uint32_t* a,
                                                uint32_t b0, uint32_t b1) {
    asm volatile(
        "mma.sync.aligned.m16n8k16.row.col.f32.f16.f16.f32 "
        "{%0,%1,%2,%3},{%4,%5,%6,%7},{%8,%9},{%0,%1,%2,%3};"
        : "+f"(c[0]), "+f"(c[1]), "+f"(c[2]), "+f"(c[3])
        : "r"(a[0]), "r"(a[1]), "r"(a[2]), "r"(a[3]), "r"(b0), "r"(b1));
}

// ---- prepass: f32 K,V -> fp16 scratch (grid (4096,2) x 256) ----
__global__ void cvt16(const float* __restrict__ K, const float* __restrict__ V) {
    size_t i = (size_t)blockIdx.x * blockDim.x + threadIdx.x;   // 8-float chunk
    const float4* src = (blockIdx.y == 0) ? (const float4*)K : (const float4*)V;
    uint4* dst = (blockIdx.y == 0) ? (uint4*)g_k16 : (uint4*)g_v16;
    float4 a = src[2 * i], b = src[2 * i + 1];
    uint4 h;
    h.x = pk(a.x, a.y); h.y = pk(a.z, a.w);
    h.z = pk(b.x, b.y); h.w = pk(b.z, b.w);
    dst[i] = h;
}

__global__ __launch_bounds__(128, 2)
void fa_fp16_v4(const float* __restrict__ Q,
                const int* __restrict__ to_mask,
                float* __restrict__ O) {
    extern __shared__ char smem[];
    const uint32_t sb = s2u(smem);

    const int tid  = threadIdx.x;
    const int w    = tid >> 5;
    const int lane = tid & 31;
    const int g    = lane >> 2;
    const int t    = lane & 3;
    const int qt   = (int)gridDim.x - 1 - (int)blockIdx.x;   // heavy tiles first
    const int bh   = blockIdx.y;
    const int msk  = to_mask[0];

    const float* Qb = Q + ((size_t)bh * S_ + (size_t)qt * BR) * D_;
    const unsigned short* Kb = g_k16 + (size_t)bh * S_ * D_;
    const unsigned short* Vb = g_v16 + (size_t)bh * S_ * D_;

    const int ntiles = msk ? (2 * qt + 2) : (S_ / BC);

    // ---- issue tile 0 (fp16 K,V -> buf0): 512 chunks each, 4/thread ----
    #pragma unroll
    for (int i = 0; i < 4; i++) {
        int f = tid + i * 128;                   // chunk idx 0..511
        int row = f >> 3, c = f & 7;
        cpa16(sb + row * RSTRIDE + c * 16,        Kb + row * D_ + c * 8);
        cpa16(sb + 9216 + row * RSTRIDE + c * 16, Vb + row * D_ + c * 8);
    }
    asm volatile("cp.async.commit_group;" ::: "memory");

    // ---- stage Q (128x64): f32 gmem -> scaled fp16 into buf1 region ----
    const float QSC = 0.125f * 1.44269504088896341f;      // 1/sqrt(64) * log2(e)
    {
        const float4* Q4 = reinterpret_cast<const float4*>(Qb);
        char* q16 = smem + BUFB;
        #pragma unroll
        for (int i = 0; i < 8; i++) {
            int ci = tid + i * 128;                        // 16B-chunk idx (0..1023)
            float4 x = Q4[2 * ci];
            float4 y = Q4[2 * ci + 1];
            uint4 h;
            h.x = pk(x.x * QSC, x.y * QSC);
            h.y = pk(x.z * QSC, x.w * QSC);
            h.z = pk(y.x * QSC, y.y * QSC);
            h.w = pk(y.z * QSC, y.w * QSC);
            *reinterpret_cast<uint4*>(q16 + (ci >> 3) * RSTRIDE + (ci & 7) * 16) = h;
        }
    }
    __syncthreads();

    // two m16 row-tiles per warp: rows w*32 + tb*16 + [0..16)
    uint32_t qa[2][4][4];
    #pragma unroll
    for (int tb = 0; tb < 2; tb++) {
        uint32_t qbase = sb + BUFB
                       + (w * 32 + tb * 16 + (lane & 15)) * RSTRIDE + (lane >> 4) * 16;
        #pragma unroll
        for (int ks = 0; ks < 4; ks++) ldm4(qa[tb][ks], qbase + ks * 32);
    }
    __syncthreads();                              // buf1 region free for tile 1

    // ---- issue tile 1 -> buf1 ----
    if (ntiles > 1) {
        const unsigned short* Kt = Kb + (size_t)BC * D_;
        const unsigned short* Vt = Vb + (size_t)BC * D_;
        #pragma unroll
        for (int i = 0; i < 4; i++) {
            int f = tid + i * 128;
            int row = f >> 3, c = f & 7;
            cpa16(sb + BUFB + row * RSTRIDE + c * 16,        Kt + row * D_ + c * 8);
            cpa16(sb + BUFB + 9216 + row * RSTRIDE + c * 16, Vt + row * D_ + c * 8);
        }
        asm volatile("cp.async.commit_group;" ::: "memory");
    }

    float o[2][8][4];
    #pragma unroll
    for (int tb = 0; tb < 2; tb++)
        #pragma unroll
        for (int nt = 0; nt < 8; nt++)
            { o[tb][nt][0]=0.f; o[tb][nt][1]=0.f; o[tb][nt][2]=0.f; o[tb][nt][3]=0.f; }
    float m[2][2] = { {-1e30f, -1e30f}, {-1e30f, -1e30f} };
    float l[2][2] = { {0.f, 0.f}, {0.f, 0.f} };

    // per-thread ldmatrix base addrs (buffer 0; add (j&1)*BUFB per iter)
    const uint32_t kfb = sb + (lane & 7) * RSTRIDE + (lane >> 3) * 16;
    const uint32_t vfb = sb + 9216 + lane * RSTRIDE;

    for (int j = 0; j < ntiles; j++) {
        if (j + 1 < ntiles)
            asm volatile("cp.async.wait_group 1;" ::: "memory");
        else
            asm volatile("cp.async.wait_group 0;" ::: "memory");
        __syncthreads();                          // tile j landed; visible to all

        const uint32_t bb = (uint32_t)(j & 1) * BUFB;

        // ---- S = Q K^T : K frags shared by both row-tiles ----
        float s[2][8][4];
        #pragma unroll
        for (int tb = 0; tb < 2; tb++)
            #pragma unroll
            for (int nt = 0; nt < 8; nt++)
                { s[tb][nt][0]=0.f; s[tb][nt][1]=0.f; s[tb][nt][2]=0.f; s[tb][nt][3]=0.f; }
        #pragma unroll
        for (int nt = 0; nt < 8; nt++) {
            uint32_t b[8];
            ldm4(b,     kfb + bb + nt * (8 * RSTRIDE));
            ldm4(b + 4, kfb + bb + nt * (8 * RSTRIDE) + 64);
            #pragma unroll
            for (int ks = 0; ks < 4; ks++) {
                mma16816(s[0][nt], qa[0][ks], b[2*ks], b[2*ks+1]);
                mma16816(s[1][nt], qa[1][ks], b[2*ks], b[2*ks+1]);
            }
        }

        // ---- causal mask (diagonal region spans key tiles 2qt, 2qt+1) ----
        if (msk && j >= 2 * qt) {
            #pragma unroll
            for (int tb = 0; tb < 2; tb++) {
                const int row0 = qt * BR + w * 32 + tb * 16 + g;
                #pragma unroll
                for (int nt = 0; nt < 8; nt++) {
                    int col = j * BC + nt * 8 + 2 * t;
                    if (col     > row0)     s[tb][nt][0] = -1e30f;
                    if (col + 1 > row0)     s[tb][nt][1] = -1e30f;
                    if (col     > row0 + 8) s[tb][nt][2] = -1e30f;
                    if (col + 1 > row0 + 8) s[tb][nt][3] = -1e30f;
                }
            }
        }

        // ---- online softmax (base-2): fp16x2 exp, rowsum via ones-MMA ----
        uint32_t pa[2][4][4];
        #pragma unroll
        for (int tb = 0; tb < 2; tb++) {
            float a0, a1, b0_, b1_;
            a0  = fmaxf(fmaxf(s[tb][0][0], s[tb][0][1]), fmaxf(s[tb][1][0], s[tb][1][1]));
            b0_ = fmaxf(fmaxf(s[tb][2][0], s[tb][2][1]), fmaxf(s[tb][3][0], s[tb][3][1]));
            a1  = fmaxf(fmaxf(s[tb][4][0], s[tb][4][1]), fmaxf(s[tb][5][0], s[tb][5][1]));
            b1_ = fmaxf(fmaxf(s[tb][6][0], s[tb][6][1]), fmaxf(s[tb][7][0], s[tb][7][1]));
            float tm0 = fmaxf(fmaxf(a0, b0_), fmaxf(a1, b1_));
            a0  = fmaxf(fmaxf(s[tb][0][2], s[tb][0][3]), fmaxf(s[tb][1][2], s[tb][1][3]));
            b0_ = fmaxf(fmaxf(s[tb][2][2], s[tb][2][3]), fmaxf(s[tb][3][2], s[tb][3][3]));
            a1  = fmaxf(fmaxf(s[tb][4][2], s[tb][4][3]), fmaxf(s[tb][5][2], s[tb][5][3]));
            b1_ = fmaxf(fmaxf(s[tb][6][2], s[tb][6][3]), fmaxf(s[tb][7][2], s[tb][7][3]));
            float tm1 = fmaxf(fmaxf(a0, b0_), fmaxf(a1, b1_));
            #pragma unroll
            for (int off = 1; off < 4; off <<= 1) {
                tm0 = fmaxf(tm0, __shfl_xor_sync(0xffffffffu, tm0, off));
                tm1 = fmaxf(tm1, __shfl_xor_sync(0xffffffffu, tm1, off));
            }
            const float mn0 = fmaxf(m[tb][0], tm0), mn1 = fmaxf(m[tb][1], tm1);
            const float c0 = ex2f(m[tb][0] - mn0), c1 = ex2f(m[tb][1] - mn1);

            // pa = exp2(s - mn) as f16x2; rowsum by MMA against ones
            float rs[4] = {0.f, 0.f, 0.f, 0.f};
            #pragma unroll
            for (int ks = 0; ks < 4; ks++) {
                pa[tb][ks][0] = hex2(pk(s[tb][2*ks][0]   - mn0, s[tb][2*ks][1]   - mn0));
                pa[tb][ks][1] = hex2(pk(s[tb][2*ks][2]   - mn1, s[tb][2*ks][3]   - mn1));
                pa[tb][ks][2] = hex2(pk(s[tb][2*ks+1][0] - mn0, s[tb][2*ks+1][1] - mn0));
                pa[tb][ks][3] = hex2(pk(s[tb][2*ks+1][2] - mn1, s[tb][2*ks+1][3] - mn1));
                mma16816(rs, pa[tb][ks], ONES16, ONES16);
            }
            // rs[0]/rs[2]: complete row sums (MMA reduced across the quad)
            l[tb][0] = l[tb][0] * c0 + rs[0];
            l[tb][1] = l[tb][1] * c1 + rs[2];
            m[tb][0] = mn0;  m[tb][1] = mn1;
            #pragma unroll
            for (int nt = 0; nt < 8; nt++) {
                o[tb][nt][0] *= c0; o[tb][nt][1] *= c0;
                o[tb][nt][2] *= c1; o[tb][nt][3] *= c1;
            }
        }

        // ---- O += P V : V frags shared by both row-tiles ----
        #pragma unroll
        for (int nt = 0; nt < 8; nt++) {
            uint32_t b[8];
            ldm4t(b,     vfb + bb + nt * 16);               // s rows 0..31
            ldm4t(b + 4, vfb + bb + nt * 16 + 32 * RSTRIDE);// s rows 32..63
            #pragma unroll
            for (int ks = 0; ks < 4; ks++) {
                mma16816(o[0][nt], pa[0][ks], b[2*ks], b[2*ks+1]);
                mma16816(o[1][nt], pa[1][ks], b[2*ks], b[2*ks+1]);
            }
        }
        __syncthreads();                          // buf[j&1] fully consumed

        // ---- issue tile j+2 -> buf[j&1] ----
        if (j + 2 < ntiles) {
            const unsigned short* Kt = Kb + (size_t)(j + 2) * BC * D_;
            const unsigned short* Vt = Vb + (size_t)(j + 2) * BC * D_;
            #pragma unroll
            for (int i = 0; i < 4; i++) {
                int f = tid + i * 128;
                int row = f >> 3, c = f & 7;
                cpa16(sb + bb + row * RSTRIDE + c * 16,        Kt + row * D_ + c * 8);
                cpa16(sb + bb + 9216 + row * RSTRIDE + c * 16, Vt + row * D_ + c * 8);
            }
            asm volatile("cp.async.commit_group;" ::: "memory");
        }
    }

    // ---- epilogue (l is already a full row sum; no shuffle needed) ----
    float* Ob = O + (size_t)bh * S_ * D_;
    #pragma unroll
    for (int tb = 0; tb < 2; tb++) {
        const float inv0 = 1.f / l[tb][0], inv1 = 1.f / l[tb][1];
        const int row0 = qt * BR + w * 32 + tb * 16 + g;
        #pragma unroll
        for (int nt = 0; nt < 8; nt++) {
            int col = nt * 8 + 2 * t;
            *reinterpret_cast<float2*>(Ob + (size_t)row0 * D_ + col) =
                make_float2(o[tb][nt][0] * inv0, o[tb][nt][1] * inv0);
            *reinterpret_cast<float2*>(Ob + (size_t)(row0 + 8) * D_ + col) =
                make_float2(o[tb][nt][2] * inv1, o[tb][nt][3] * inv1);
        }
    }
}

extern "C" void kernel_launch(void* const* d_in, const int* in_sizes, int n_in,
                              void* d_out, int out_size) {
    const float* Q = (const float*)d_in[0];
    const float* K = (const float*)d_in[1];
    const float* V = (const float*)d_in[2];
    const int* msk = (const int*)d_in[3];
    float* O = (float*)d_out;

    // prepass: K,V f32 -> fp16 scratch
    dim3 cg((B_ * H_ * S_ * D_ / 8) / 256, 2);
    cvt16<<<cg, 256>>>(K, V);

    cudaFuncSetAttribute(fa_fp16_v4, cudaFuncAttributeMaxDynamicSharedMemorySize, SM_BYTES);
    dim3 grid(S_ / BR, B_ * H_);
    fa_fp16_v4<<<grid, 128, SM_BYTES>>>(Q, msk, O);
}